// round 1
// baseline (speedup 1.0000x reference)
#include <cuda_runtime.h>

#define BATCH 16
#define LQ    512
#define LC    2048
#define DIM   1024

#define BK    16
#define SMS   132   // smem row stride (128 + 4 pad)

// Scratch for logits / attention weights: 16*2048*512 floats = 64 MB
__device__ float g_attn[(size_t)BATCH * LC * LQ];

// ---------------------------------------------------------------------------
// GEMM1 (NT): E[b,c,q] = sum_d ctx[b,c,d] * q[b,q,d]   -> g_attn
// Tile 128x128, K-tile 16, 256 threads, 8x8 per thread, double-buffered.
// ---------------------------------------------------------------------------
__global__ __launch_bounds__(256, 2)
void ba_gemm1(const float* __restrict__ ctx, const float* __restrict__ qst)
{
    __shared__ __align__(16) float As[2][BK][SMS];
    __shared__ __align__(16) float Bs[2][BK][SMS];

    const int b     = blockIdx.z;
    const int cTile = blockIdx.y * 128;
    const int qTile = blockIdx.x * 128;

    const float* Ag = ctx + ((size_t)b * LC + cTile) * DIM;
    const float* Bg = qst + ((size_t)b * LQ + qTile) * DIM;

    const int tid = threadIdx.x;
    const int tx  = tid & 15;
    const int ty  = tid >> 4;
    const int lr  = tid >> 2;          // 0..63 : row within tile
    const int lk  = (tid & 3) * 4;     // 0,4,8,12 : k offset

    float acc[8][8];
#pragma unroll
    for (int i = 0; i < 8; i++)
#pragma unroll
        for (int j = 0; j < 8; j++) acc[i][j] = 0.f;

    float4 pa0, pa1, pb0, pb1;

    // prologue: tile 0
    pa0 = *(const float4*)(Ag + (size_t)lr        * DIM + lk);
    pa1 = *(const float4*)(Ag + (size_t)(lr + 64) * DIM + lk);
    pb0 = *(const float4*)(Bg + (size_t)lr        * DIM + lk);
    pb1 = *(const float4*)(Bg + (size_t)(lr + 64) * DIM + lk);

    As[0][lk+0][lr]    = pa0.x; As[0][lk+1][lr]    = pa0.y; As[0][lk+2][lr]    = pa0.z; As[0][lk+3][lr]    = pa0.w;
    As[0][lk+0][lr+64] = pa1.x; As[0][lk+1][lr+64] = pa1.y; As[0][lk+2][lr+64] = pa1.z; As[0][lk+3][lr+64] = pa1.w;
    Bs[0][lk+0][lr]    = pb0.x; Bs[0][lk+1][lr]    = pb0.y; Bs[0][lk+2][lr]    = pb0.z; Bs[0][lk+3][lr]    = pb0.w;
    Bs[0][lk+0][lr+64] = pb1.x; Bs[0][lk+1][lr+64] = pb1.y; Bs[0][lk+2][lr+64] = pb1.z; Bs[0][lk+3][lr+64] = pb1.w;
    __syncthreads();

    int buf = 0;
    const int NT = DIM / BK;   // 64
    for (int kt = 0; kt < NT; kt++) {
        if (kt + 1 < NT) {
            const float* ap = Ag + (kt + 1) * BK;
            const float* bp = Bg + (kt + 1) * BK;
            pa0 = *(const float4*)(ap + (size_t)lr        * DIM + lk);
            pa1 = *(const float4*)(ap + (size_t)(lr + 64) * DIM + lk);
            pb0 = *(const float4*)(bp + (size_t)lr        * DIM + lk);
            pb1 = *(const float4*)(bp + (size_t)(lr + 64) * DIM + lk);
        }
#pragma unroll
        for (int k = 0; k < BK; k++) {
            float a[8], bb[8];
            *(float4*)&a[0]  = *(const float4*)&As[buf][k][ty * 8];
            *(float4*)&a[4]  = *(const float4*)&As[buf][k][ty * 8 + 4];
            *(float4*)&bb[0] = *(const float4*)&Bs[buf][k][tx * 8];
            *(float4*)&bb[4] = *(const float4*)&Bs[buf][k][tx * 8 + 4];
#pragma unroll
            for (int i = 0; i < 8; i++)
#pragma unroll
                for (int j = 0; j < 8; j++) acc[i][j] += a[i] * bb[j];
        }
        if (kt + 1 < NT) {
            const int nb = buf ^ 1;
            As[nb][lk+0][lr]    = pa0.x; As[nb][lk+1][lr]    = pa0.y; As[nb][lk+2][lr]    = pa0.z; As[nb][lk+3][lr]    = pa0.w;
            As[nb][lk+0][lr+64] = pa1.x; As[nb][lk+1][lr+64] = pa1.y; As[nb][lk+2][lr+64] = pa1.z; As[nb][lk+3][lr+64] = pa1.w;
            Bs[nb][lk+0][lr]    = pb0.x; Bs[nb][lk+1][lr]    = pb0.y; Bs[nb][lk+2][lr]    = pb0.z; Bs[nb][lk+3][lr]    = pb0.w;
            Bs[nb][lk+0][lr+64] = pb1.x; Bs[nb][lk+1][lr+64] = pb1.y; Bs[nb][lk+2][lr+64] = pb1.z; Bs[nb][lk+3][lr+64] = pb1.w;
            __syncthreads();
        }
        buf ^= 1;
    }

    float* Ep = g_attn + ((size_t)b * LC + cTile + ty * 8) * LQ + qTile + tx * 8;
#pragma unroll
    for (int i = 0; i < 8; i++) {
        *(float4*)(Ep + (size_t)i * LQ)     = make_float4(acc[i][0], acc[i][1], acc[i][2], acc[i][3]);
        *(float4*)(Ep + (size_t)i * LQ + 4) = make_float4(acc[i][4], acc[i][5], acc[i][6], acc[i][7]);
    }
}

// ---------------------------------------------------------------------------
// Row softmax over 512 logits, in place in g_attn. One block (256 thr) per row.
// ---------------------------------------------------------------------------
__global__ __launch_bounds__(256)
void ba_softmax(void)
{
    __shared__ float red[256];
    float* p = g_attn + (size_t)blockIdx.x * LQ;
    const int t = threadIdx.x;

    float v0 = p[t];
    float v1 = p[t + 256];

    red[t] = fmaxf(v0, v1);
    __syncthreads();
#pragma unroll
    for (int s = 128; s > 0; s >>= 1) {
        if (t < s) red[t] = fmaxf(red[t], red[t + s]);
        __syncthreads();
    }
    const float mx = red[0];
    __syncthreads();

    const float e0 = __expf(v0 - mx);
    const float e1 = __expf(v1 - mx);
    red[t] = e0 + e1;
    __syncthreads();
#pragma unroll
    for (int s = 128; s > 0; s >>= 1) {
        if (t < s) red[t] += red[t + s];
        __syncthreads();
    }
    const float inv = 1.0f / red[0];
    p[t]       = e0 * inv;
    p[t + 256] = e1 * inv;
}

// ---------------------------------------------------------------------------
// GEMM2 (NN): out[b,c,1024+d] = sum_q attn[b,c,q] * qst[b,q,d]
// ---------------------------------------------------------------------------
__global__ __launch_bounds__(256, 2)
void ba_gemm2(const float* __restrict__ qst, float* __restrict__ out)
{
    __shared__ __align__(16) float As[2][BK][SMS];
    __shared__ __align__(16) float Bs[2][BK][SMS];

    const int b     = blockIdx.z;
    const int cTile = blockIdx.y * 128;
    const int dTile = blockIdx.x * 128;

    const float* Ag = g_attn + ((size_t)b * LC + cTile) * LQ;
    const float* Bg = qst + (size_t)b * LQ * DIM + dTile;

    const int tid = threadIdx.x;
    const int tx  = tid & 15;
    const int ty  = tid >> 4;
    const int lr  = tid >> 2;          // A row
    const int lk  = (tid & 3) * 4;     // A k offset
    const int bk  = tid >> 5;          // 0..7 : B k row
    const int bn  = (tid & 31) * 4;    // B n offset

    float acc[8][8];
#pragma unroll
    for (int i = 0; i < 8; i++)
#pragma unroll
        for (int j = 0; j < 8; j++) acc[i][j] = 0.f;

    float4 pa0, pa1, pb0, pb1;

    pa0 = *(const float4*)(Ag + (size_t)lr        * LQ + lk);
    pa1 = *(const float4*)(Ag + (size_t)(lr + 64) * LQ + lk);
    pb0 = *(const float4*)(Bg + (size_t)bk       * DIM + bn);
    pb1 = *(const float4*)(Bg + (size_t)(bk + 8) * DIM + bn);

    As[0][lk+0][lr]    = pa0.x; As[0][lk+1][lr]    = pa0.y; As[0][lk+2][lr]    = pa0.z; As[0][lk+3][lr]    = pa0.w;
    As[0][lk+0][lr+64] = pa1.x; As[0][lk+1][lr+64] = pa1.y; As[0][lk+2][lr+64] = pa1.z; As[0][lk+3][lr+64] = pa1.w;
    *(float4*)&Bs[0][bk][bn]     = pb0;
    *(float4*)&Bs[0][bk + 8][bn] = pb1;
    __syncthreads();

    int buf = 0;
    const int NT = LQ / BK;   // 32
    for (int kt = 0; kt < NT; kt++) {
        if (kt + 1 < NT) {
            const float* ap = Ag + (kt + 1) * BK;
            const float* bp = Bg + (size_t)(kt + 1) * BK * DIM;
            pa0 = *(const float4*)(ap + (size_t)lr        * LQ + lk);
            pa1 = *(const float4*)(ap + (size_t)(lr + 64) * LQ + lk);
            pb0 = *(const float4*)(bp + (size_t)bk       * DIM + bn);
            pb1 = *(const float4*)(bp + (size_t)(bk + 8) * DIM + bn);
        }
#pragma unroll
        for (int k = 0; k < BK; k++) {
            float a[8], bb[8];
            *(float4*)&a[0]  = *(const float4*)&As[buf][k][ty * 8];
            *(float4*)&a[4]  = *(const float4*)&As[buf][k][ty * 8 + 4];
            *(float4*)&bb[0] = *(const float4*)&Bs[buf][k][tx * 8];
            *(float4*)&bb[4] = *(const float4*)&Bs[buf][k][tx * 8 + 4];
#pragma unroll
            for (int i = 0; i < 8; i++)
#pragma unroll
                for (int j = 0; j < 8; j++) acc[i][j] += a[i] * bb[j];
        }
        if (kt + 1 < NT) {
            const int nb = buf ^ 1;
            As[nb][lk+0][lr]    = pa0.x; As[nb][lk+1][lr]    = pa0.y; As[nb][lk+2][lr]    = pa0.z; As[nb][lk+3][lr]    = pa0.w;
            As[nb][lk+0][lr+64] = pa1.x; As[nb][lk+1][lr+64] = pa1.y; As[nb][lk+2][lr+64] = pa1.z; As[nb][lk+3][lr+64] = pa1.w;
            *(float4*)&Bs[nb][bk][bn]     = pb0;
            *(float4*)&Bs[nb][bk + 8][bn] = pb1;
            __syncthreads();
        }
        buf ^= 1;
    }

    // write to second half of the concatenated output (row width 2*DIM)
    float* Op = out + ((size_t)b * LC + cTile + ty * 8) * (2 * DIM) + DIM + dTile + tx * 8;
#pragma unroll
    for (int i = 0; i < 8; i++) {
        *(float4*)(Op + (size_t)i * (2 * DIM))     = make_float4(acc[i][0], acc[i][1], acc[i][2], acc[i][3]);
        *(float4*)(Op + (size_t)i * (2 * DIM) + 4) = make_float4(acc[i][4], acc[i][5], acc[i][6], acc[i][7]);
    }
}

// ---------------------------------------------------------------------------
// Copy context into first half of the output rows. float4 granularity.
// ---------------------------------------------------------------------------
__global__ __launch_bounds__(256)
void ba_copy(const float* __restrict__ ctx, float* __restrict__ out)
{
    const size_t i   = (size_t)blockIdx.x * 256 + threadIdx.x;   // float4 index
    const size_t row = i / (DIM / 4);
    const size_t col = i % (DIM / 4);
    const float4* s  = (const float4*)ctx;
    float4* d        = (float4*)out;
    d[row * (2 * DIM / 4) + col] = s[i];
}

// ---------------------------------------------------------------------------
extern "C" void kernel_launch(void* const* d_in, const int* in_sizes, int n_in,
                              void* d_out, int out_size)
{
    const float* question = (const float*)d_in[0];
    const float* context  = (const float*)d_in[1];
    // defensive: question has 8.4M elems, context 33.6M
    if (in_sizes[0] > in_sizes[1]) {
        const float* t = question; question = context; context = t;
    }
    float* out = (float*)d_out;

    // independent of the GEMM chain; launch first
    ba_copy<<<(BATCH * LC * (DIM / 4)) / 256, 256>>>(context, out);

    ba_gemm1<<<dim3(LQ / 128, LC / 128, BATCH), 256>>>(context, question);
    ba_softmax<<<BATCH * LC, 256>>>();
    ba_gemm2<<<dim3(DIM / 128, LC / 128, BATCH), 256>>>(question, out);
}

// round 7
// speedup vs baseline: 2.2067x; 2.2067x over previous
#include <cuda_runtime.h>
#include <cuda_bf16.h>
#include <cstdint>

#define BATCH 16
#define LQ    512
#define LC    2048
#define DIM   1024

// fp32 logits / softmax weights scratch (device-side only; NEVER passed from host)
__device__ float g_attn[(size_t)BATCH * LC * LQ];

// ---------------------------------------------------------------------------
// helpers
// ---------------------------------------------------------------------------
__device__ __forceinline__ void ldm4(uint32_t a, uint32_t& r0, uint32_t& r1,
                                     uint32_t& r2, uint32_t& r3) {
    asm volatile("ldmatrix.sync.aligned.m8n8.x4.shared.b16 {%0,%1,%2,%3}, [%4];"
                 : "=r"(r0), "=r"(r1), "=r"(r2), "=r"(r3) : "r"(a));
}
__device__ __forceinline__ void ldm4t(uint32_t a, uint32_t& r0, uint32_t& r1,
                                      uint32_t& r2, uint32_t& r3) {
    asm volatile("ldmatrix.sync.aligned.m8n8.x4.trans.shared.b16 {%0,%1,%2,%3}, [%4];"
                 : "=r"(r0), "=r"(r1), "=r"(r2), "=r"(r3) : "r"(a));
}
__device__ __forceinline__ void mma16816(float* c, uint32_t a0, uint32_t a1, uint32_t a2,
                                         uint32_t a3, uint32_t b0, uint32_t b1) {
    asm volatile(
        "mma.sync.aligned.m16n8k16.row.col.f32.bf16.bf16.f32 "
        "{%0,%1,%2,%3}, {%4,%5,%6,%7}, {%8,%9}, {%0,%1,%2,%3};"
        : "+f"(c[0]), "+f"(c[1]), "+f"(c[2]), "+f"(c[3])
        : "r"(a0), "r"(a1), "r"(a2), "r"(a3), "r"(b0), "r"(b1));
}
__device__ __forceinline__ uint32_t smem_u32(const void* p) {
    uint32_t a;
    asm("{ .reg .u64 t; cvta.to.shared.u64 t, %1; cvt.u32.u64 %0, t; }" : "=r"(a) : "l"(p));
    return a;
}
// split float4 into packed bf16 hi pair-words and lo pair-words
__device__ __forceinline__ void split4(float4 v, uint32_t& h01, uint32_t& h23,
                                       uint32_t& l01, uint32_t& l23) {
    __nv_bfloat16 hx = __float2bfloat16(v.x), hy = __float2bfloat16(v.y);
    __nv_bfloat16 hz = __float2bfloat16(v.z), hw = __float2bfloat16(v.w);
    float lx = v.x - __bfloat162float(hx), ly = v.y - __bfloat162float(hy);
    float lz = v.z - __bfloat162float(hz), lw = v.w - __bfloat162float(hw);
    __nv_bfloat162 H0(hx, hy), H1(hz, hw);
    __nv_bfloat162 L0 = __floats2bfloat162_rn(lx, ly), L1 = __floats2bfloat162_rn(lz, lw);
    h01 = *(uint32_t*)&H0; h23 = *(uint32_t*)&H1;
    l01 = *(uint32_t*)&L0; l23 = *(uint32_t*)&L1;
}

// ---------------------------------------------------------------------------
// Split-bf16 mma GEMM reading fp32 operands directly (in-kernel conversion).
// C = A(fp32,[m][k]) * B^T with fp32 accumulate via 3 bf16 products.
// FIRST : logits[c][q] = ctx[c][d] . q[q][d]           K=1024 -> g_attn (device sym)
// !FIRST: attn [c][d] = w[c][q] . q[q][d]  (B=[k][n])  K=512  -> out right half
// A/C device-scratch bindings resolved IN DEVICE CODE (host passes only
// harness-owned pointers).
// CTA 128x128, BK=16, 8 warps (64x32 warp tile), double-buffered static smem.
// ---------------------------------------------------------------------------
#define AROWB 48                   // 16 bf16 = 32B + 16B pad (conflict-free)
#define BROWB2 272                 // second-gemm B rows: 256B + 16B pad

template <bool FIRST>
__global__ __launch_bounds__(256)
void ba_mma(const float* __restrict__ actx, const float* __restrict__ qst,
            float* __restrict__ gout)
{
    constexpr int KT = FIRST ? DIM : LQ;
    constexpr int NT = KT / 16;
    constexpr int OUTSTRIDE = FIRST ? LQ : 2 * DIM;
    constexpr int OUTOFF    = FIRST ? 0  : DIM;
    // stage layout: [A_hi 6144][A_lo 6144][B_hi][B_lo]
    constexpr int BHALF = FIRST ? (128 * AROWB) : (16 * BROWB2);   // 6144 / 4352
    constexpr int STAGE = 2 * 128 * AROWB + 2 * BHALF;             // 24576 / 20992
    constexpr int AH = 0, AL = 128 * AROWB, BH = 2 * 128 * AROWB, BL = BH + BHALF;

    __shared__ __align__(16) char sm[2 * STAGE];
    const uint32_t sb = smem_u32(sm);

    const int tid  = threadIdx.x;
    const int lane = tid & 31;
    const int warp = tid >> 5;
    const int wm   = warp & 1;         // m offset 64*wm
    const int wn   = warp >> 1;        // n offset 32*wn
    const int b  = blockIdx.z;
    const int yT = blockIdx.y;
    const int xT = blockIdx.x;

    // DEVICE-SIDE symbol binding (the R3-R6 bug was doing this from host)
    const float* Ag = FIRST ? actx : (const float*)g_attn;
    float*       Cg = FIRST ? (float*)g_attn : gout;

    const float* Abase = Ag + ((size_t)b * LC + (size_t)yT * 128) * KT;
    const float* Bbase = FIRST
        ? qst + ((size_t)b * LQ + (size_t)xT * 128) * DIM      // rows n=q, k=d
        : qst + (size_t)b * LQ * DIM + (size_t)xT * 128;       // rows k=q, cols n=d

    // per-thread load coordinates
    const int ar = tid >> 2;           // 0..63  (A row; +64 for 2nd chunk)
    const int ac = tid & 3;            // float4 index along k
    const int kr = tid >> 5;           // 0..7   (B-second k-row; +8 for 2nd chunk)
    const int nc = tid & 31;           // float4 index along n

    auto sts_stage = [&](uint32_t s0, float4 pa0, float4 pa1, float4 pb0, float4 pb1) {
        uint32_t h0, h1, l0, l1;
        split4(pa0, h0, h1, l0, l1);
        *(uint2*)(sm + (s0 + AH + ar * AROWB + ac * 8))        = make_uint2(h0, h1);
        *(uint2*)(sm + (s0 + AL + ar * AROWB + ac * 8))        = make_uint2(l0, l1);
        split4(pa1, h0, h1, l0, l1);
        *(uint2*)(sm + (s0 + AH + (ar + 64) * AROWB + ac * 8)) = make_uint2(h0, h1);
        *(uint2*)(sm + (s0 + AL + (ar + 64) * AROWB + ac * 8)) = make_uint2(l0, l1);
        if (FIRST) {
            split4(pb0, h0, h1, l0, l1);
            *(uint2*)(sm + (s0 + BH + ar * AROWB + ac * 8))        = make_uint2(h0, h1);
            *(uint2*)(sm + (s0 + BL + ar * AROWB + ac * 8))        = make_uint2(l0, l1);
            split4(pb1, h0, h1, l0, l1);
            *(uint2*)(sm + (s0 + BH + (ar + 64) * AROWB + ac * 8)) = make_uint2(h0, h1);
            *(uint2*)(sm + (s0 + BL + (ar + 64) * AROWB + ac * 8)) = make_uint2(l0, l1);
        } else {
            split4(pb0, h0, h1, l0, l1);
            *(uint2*)(sm + (s0 + BH + kr * BROWB2 + nc * 8))       = make_uint2(h0, h1);
            *(uint2*)(sm + (s0 + BL + kr * BROWB2 + nc * 8))       = make_uint2(l0, l1);
            split4(pb1, h0, h1, l0, l1);
            *(uint2*)(sm + (s0 + BH + (kr + 8) * BROWB2 + nc * 8)) = make_uint2(h0, h1);
            *(uint2*)(sm + (s0 + BL + (kr + 8) * BROWB2 + nc * 8)) = make_uint2(l0, l1);
        }
    };
    auto ldg_tiles = [&](int kt, float4& pa0, float4& pa1, float4& pb0, float4& pb1) {
        pa0 = *(const float4*)(Abase + (size_t)ar * KT + kt * 16 + ac * 4);
        pa1 = *(const float4*)(Abase + (size_t)(ar + 64) * KT + kt * 16 + ac * 4);
        if (FIRST) {
            pb0 = *(const float4*)(Bbase + (size_t)ar * DIM + kt * 16 + ac * 4);
            pb1 = *(const float4*)(Bbase + (size_t)(ar + 64) * DIM + kt * 16 + ac * 4);
        } else {
            pb0 = *(const float4*)(Bbase + (size_t)(kt * 16 + kr) * DIM + nc * 4);
            pb1 = *(const float4*)(Bbase + (size_t)(kt * 16 + kr + 8) * DIM + nc * 4);
        }
    };

    float acc[4][4][4];
#pragma unroll
    for (int m = 0; m < 4; m++)
#pragma unroll
        for (int n = 0; n < 4; n++)
#pragma unroll
            for (int j = 0; j < 4; j++) acc[m][n][j] = 0.f;

    // prologue: stage 0
    {
        float4 a0, a1, b0, b1;
        ldg_tiles(0, a0, a1, b0, b1);
        sts_stage(0, a0, a1, b0, b1);
    }
    __syncthreads();

    const int lrow = lane & 15;
    const int lkb  = lane & 16;         // second 16B chunk (k+8 / n+8)
    constexpr int I1 = FIRST ? 2 : 1;   // ntile0 second b-reg
    constexpr int J0 = FIRST ? 1 : 2;   // ntile1 first b-reg

    for (int kt = 0; kt < NT; kt++) {
        const uint32_t s0 = (kt & 1) * STAGE;

        float4 pa0, pa1, pb0, pb1;
        if (kt + 1 < NT) ldg_tiles(kt + 1, pa0, pa1, pb0, pb1);

        uint32_t ah[4][4], al[4][4];
#pragma unroll
        for (int mt = 0; mt < 4; mt++) {
            uint32_t ra = sb + s0 + AH + (wm * 64 + mt * 16 + lrow) * AROWB + lkb;
            ldm4(ra, ah[mt][0], ah[mt][1], ah[mt][2], ah[mt][3]);
            uint32_t rl = sb + s0 + AL + (wm * 64 + mt * 16 + lrow) * AROWB + lkb;
            ldm4(rl, al[mt][0], al[mt][1], al[mt][2], al[mt][3]);
        }
#pragma unroll
        for (int p = 0; p < 2; p++) {
            uint32_t bh[4], bl[4];
            if (FIRST) {
                uint32_t rb = sb + s0 + BH + (wn * 32 + p * 16 + lrow) * AROWB + lkb;
                ldm4(rb, bh[0], bh[1], bh[2], bh[3]);
                uint32_t rc = sb + s0 + BL + (wn * 32 + p * 16 + lrow) * AROWB + lkb;
                ldm4(rc, bl[0], bl[1], bl[2], bl[3]);
            } else {
                uint32_t rb = sb + s0 + BH + lrow * BROWB2 + (wn * 32 + p * 16) * 2 + lkb;
                ldm4t(rb, bh[0], bh[1], bh[2], bh[3]);
                uint32_t rc = sb + s0 + BL + lrow * BROWB2 + (wn * 32 + p * 16) * 2 + lkb;
                ldm4t(rc, bl[0], bl[1], bl[2], bl[3]);
            }
#pragma unroll
            for (int mt = 0; mt < 4; mt++) {
                mma16816(acc[mt][2 * p],     ah[mt][0], ah[mt][1], ah[mt][2], ah[mt][3], bh[0],  bh[I1]);
                mma16816(acc[mt][2 * p + 1], ah[mt][0], ah[mt][1], ah[mt][2], ah[mt][3], bh[J0], bh[3]);
                mma16816(acc[mt][2 * p],     al[mt][0], al[mt][1], al[mt][2], al[mt][3], bh[0],  bh[I1]);
                mma16816(acc[mt][2 * p + 1], al[mt][0], al[mt][1], al[mt][2], al[mt][3], bh[J0], bh[3]);
                mma16816(acc[mt][2 * p],     ah[mt][0], ah[mt][1], ah[mt][2], ah[mt][3], bl[0],  bl[I1]);
                mma16816(acc[mt][2 * p + 1], ah[mt][0], ah[mt][1], ah[mt][2], ah[mt][3], bl[J0], bl[3]);
            }
        }

        if (kt + 1 < NT) sts_stage(((kt + 1) & 1) * STAGE, pa0, pa1, pb0, pb1);
        __syncthreads();
    }

    // epilogue (standard m16n8 C layout)
    const size_t rbase = (size_t)b * LC + (size_t)yT * 128 + wm * 64 + (lane >> 2);
    const int    cbase = OUTOFF + xT * 128 + wn * 32 + (lane & 3) * 2;
#pragma unroll
    for (int mt = 0; mt < 4; mt++) {
#pragma unroll
        for (int nt = 0; nt < 4; nt++) {
            size_t r0 = (rbase + mt * 16) * OUTSTRIDE + cbase + nt * 8;
            *(float2*)(Cg + r0)                    = make_float2(acc[mt][nt][0], acc[mt][nt][1]);
            *(float2*)(Cg + r0 + 8ull * OUTSTRIDE) = make_float2(acc[mt][nt][2], acc[mt][nt][3]);
        }
    }
}

// ---------------------------------------------------------------------------
// Row softmax over 512 logits, in place in g_attn (device symbol, device code).
// ---------------------------------------------------------------------------
__global__ __launch_bounds__(256)
void ba_softmax(void)
{
    __shared__ float red[256];
    float* p = g_attn + (size_t)blockIdx.x * LQ;
    const int t = threadIdx.x;

    float v0 = p[t];
    float v1 = p[t + 256];

    red[t] = fmaxf(v0, v1);
    __syncthreads();
#pragma unroll
    for (int s = 128; s > 0; s >>= 1) {
        if (t < s) red[t] = fmaxf(red[t], red[t + s]);
        __syncthreads();
    }
    const float mx = red[0];
    __syncthreads();

    const float e0 = __expf(v0 - mx);
    const float e1 = __expf(v1 - mx);
    red[t] = e0 + e1;
    __syncthreads();
#pragma unroll
    for (int s = 128; s > 0; s >>= 1) {
        if (t < s) red[t] += red[t + s];
        __syncthreads();
    }
    const float inv = 1.0f / red[0];
    p[t]       = e0 * inv;
    p[t + 256] = e1 * inv;
}

// ---------------------------------------------------------------------------
// Copy context into left half of output rows
// ---------------------------------------------------------------------------
__global__ __launch_bounds__(256)
void ba_copy(const float* __restrict__ ctx, float* __restrict__ out)
{
    const size_t i   = (size_t)blockIdx.x * 256 + threadIdx.x;   // float4 idx
    const size_t row = i / (DIM / 4);
    const size_t col = i % (DIM / 4);
    ((float4*)out)[row * (2 * DIM / 4) + col] = ((const float4*)ctx)[i];
}

// ---------------------------------------------------------------------------
extern "C" void kernel_launch(void* const* d_in, const int* in_sizes, int n_in,
                              void* d_out, int out_size)
{
    const float* question = (const float*)d_in[0];
    const float* context  = (const float*)d_in[1];
    if (in_sizes[0] > in_sizes[1]) {
        const float* t = question; question = context; context = t;
    }
    float* out = (float*)d_out;

    // left half of out (independent)
    ba_copy<<<(size_t)BATCH * LC * (DIM / 4) / 256, 256>>>(context, out);

    // logits = ctx @ q^T -> g_attn (bound in device code)
    ba_mma<true><<<dim3(LQ / 128, LC / 128, BATCH), 256>>>(context, question, nullptr);
    // softmax in place (fp32)
    ba_softmax<<<BATCH * LC, 256>>>();
    // attn_out = w @ q -> right half of out (A = g_attn bound in device code)
    ba_mma<false><<<dim3(DIM / 128, LC / 128, BATCH), 256>>>(nullptr, question, out);
}

// round 8
// speedup vs baseline: 2.3873x; 1.0818x over previous
#include <cuda_runtime.h>
#include <cuda_bf16.h>
#include <cstdint>

#define BATCH 16
#define LQ    512
#define LC    2048
#define DIM   1024

// fp32 logits / softmax weights scratch (device-side only; NEVER passed from host)
__device__ float g_attn[(size_t)BATCH * LC * LQ];

// ---------------------------------------------------------------------------
// helpers
// ---------------------------------------------------------------------------
__device__ __forceinline__ void ldm4(uint32_t a, uint32_t& r0, uint32_t& r1,
                                     uint32_t& r2, uint32_t& r3) {
    asm volatile("ldmatrix.sync.aligned.m8n8.x4.shared.b16 {%0,%1,%2,%3}, [%4];"
                 : "=r"(r0), "=r"(r1), "=r"(r2), "=r"(r3) : "r"(a));
}
__device__ __forceinline__ void ldm4t(uint32_t a, uint32_t& r0, uint32_t& r1,
                                      uint32_t& r2, uint32_t& r3) {
    asm volatile("ldmatrix.sync.aligned.m8n8.x4.trans.shared.b16 {%0,%1,%2,%3}, [%4];"
                 : "=r"(r0), "=r"(r1), "=r"(r2), "=r"(r3) : "r"(a));
}
__device__ __forceinline__ void mma16816(float* c, uint32_t a0, uint32_t a1, uint32_t a2,
                                         uint32_t a3, uint32_t b0, uint32_t b1) {
    asm volatile(
        "mma.sync.aligned.m16n8k16.row.col.f32.bf16.bf16.f32 "
        "{%0,%1,%2,%3}, {%4,%5,%6,%7}, {%8,%9}, {%0,%1,%2,%3};"
        : "+f"(c[0]), "+f"(c[1]), "+f"(c[2]), "+f"(c[3])
        : "r"(a0), "r"(a1), "r"(a2), "r"(a3), "r"(b0), "r"(b1));
}
__device__ __forceinline__ uint32_t smem_u32(const void* p) {
    uint32_t a;
    asm("{ .reg .u64 t; cvta.to.shared.u64 t, %1; cvt.u32.u64 %0, t; }" : "=r"(a) : "l"(p));
    return a;
}
// split float4 into packed bf16 hi pair-words and lo pair-words
__device__ __forceinline__ void split4(float4 v, uint32_t& h01, uint32_t& h23,
                                       uint32_t& l01, uint32_t& l23) {
    __nv_bfloat16 hx = __float2bfloat16(v.x), hy = __float2bfloat16(v.y);
    __nv_bfloat16 hz = __float2bfloat16(v.z), hw = __float2bfloat16(v.w);
    float lx = v.x - __bfloat162float(hx), ly = v.y - __bfloat162float(hy);
    float lz = v.z - __bfloat162float(hz), lw = v.w - __bfloat162float(hw);
    __nv_bfloat162 H0(hx, hy), H1(hz, hw);
    __nv_bfloat162 L0 = __floats2bfloat162_rn(lx, ly), L1 = __floats2bfloat162_rn(lz, lw);
    h01 = *(uint32_t*)&H0; h23 = *(uint32_t*)&H1;
    l01 = *(uint32_t*)&L0; l23 = *(uint32_t*)&L1;
}

// ---------------------------------------------------------------------------
// Split-bf16 mma GEMM reading fp32 operands directly (in-kernel conversion).
// C = A(fp32,[m][k]) * B^T with fp32 accumulate via 3 bf16 products.
// FIRST : logits[c][q] = ctx[c][d] . q[q][d]           K=1024 -> g_attn (device sym)
// !FIRST: attn [c][d] = w[c][q] . q[q][d]  (B=[k][n])  K=512  -> out right half,
//         PLUS fused copy of the matching 128x128 ctx tile into out left half.
// CTA 128x128, BK=16, 8 warps (64x32 warp tile), double-buffered static smem.
// ---------------------------------------------------------------------------
#define AROWB 48                   // 16 bf16 = 32B + 16B pad (conflict-free)
#define BROWB2 272                 // second-gemm B rows: 256B + 16B pad

template <bool FIRST>
__global__ __launch_bounds__(256)
void ba_mma(const float* __restrict__ actx, const float* __restrict__ qst,
            float* __restrict__ gout)
{
    constexpr int KT = FIRST ? DIM : LQ;
    constexpr int NT = KT / 16;
    constexpr int OUTSTRIDE = FIRST ? LQ : 2 * DIM;
    constexpr int OUTOFF    = FIRST ? 0  : DIM;
    constexpr int BHALF = FIRST ? (128 * AROWB) : (16 * BROWB2);   // 6144 / 4352
    constexpr int STAGE = 2 * 128 * AROWB + 2 * BHALF;             // 24576 / 20992
    constexpr int AH = 0, AL = 128 * AROWB, BH = 2 * 128 * AROWB, BL = BH + BHALF;

    __shared__ __align__(16) char sm[2 * STAGE];
    const uint32_t sb = smem_u32(sm);

    const int tid  = threadIdx.x;
    const int lane = tid & 31;
    const int warp = tid >> 5;
    const int wm   = warp & 1;         // m offset 64*wm
    const int wn   = warp >> 1;        // n offset 32*wn
    const int b  = blockIdx.z;
    const int yT = blockIdx.y;
    const int xT = blockIdx.x;

    // DEVICE-SIDE scratch binding (host passes only harness pointers)
    const float* Ag = FIRST ? actx : (const float*)g_attn;
    float*       Cg = FIRST ? (float*)g_attn : gout;

    const float* Abase = Ag + ((size_t)b * LC + (size_t)yT * 128) * KT;
    const float* Bbase = FIRST
        ? qst + ((size_t)b * LQ + (size_t)xT * 128) * DIM      // rows n=q, k=d
        : qst + (size_t)b * LQ * DIM + (size_t)xT * 128;       // rows k=q, cols n=d

    const int ar = tid >> 2;           // 0..63  (A row; +64 for 2nd chunk)
    const int ac = tid & 3;            // float4 index along k
    const int kr = tid >> 5;           // 0..7   (B-second k-row; +8 for 2nd chunk)
    const int nc = tid & 31;           // float4 index along n

    auto sts_stage = [&](uint32_t s0, float4 pa0, float4 pa1, float4 pb0, float4 pb1) {
        uint32_t h0, h1, l0, l1;
        split4(pa0, h0, h1, l0, l1);
        *(uint2*)(sm + (s0 + AH + ar * AROWB + ac * 8))        = make_uint2(h0, h1);
        *(uint2*)(sm + (s0 + AL + ar * AROWB + ac * 8))        = make_uint2(l0, l1);
        split4(pa1, h0, h1, l0, l1);
        *(uint2*)(sm + (s0 + AH + (ar + 64) * AROWB + ac * 8)) = make_uint2(h0, h1);
        *(uint2*)(sm + (s0 + AL + (ar + 64) * AROWB + ac * 8)) = make_uint2(l0, l1);
        if (FIRST) {
            split4(pb0, h0, h1, l0, l1);
            *(uint2*)(sm + (s0 + BH + ar * AROWB + ac * 8))        = make_uint2(h0, h1);
            *(uint2*)(sm + (s0 + BL + ar * AROWB + ac * 8))        = make_uint2(l0, l1);
            split4(pb1, h0, h1, l0, l1);
            *(uint2*)(sm + (s0 + BH + (ar + 64) * AROWB + ac * 8)) = make_uint2(h0, h1);
            *(uint2*)(sm + (s0 + BL + (ar + 64) * AROWB + ac * 8)) = make_uint2(l0, l1);
        } else {
            split4(pb0, h0, h1, l0, l1);
            *(uint2*)(sm + (s0 + BH + kr * BROWB2 + nc * 8))       = make_uint2(h0, h1);
            *(uint2*)(sm + (s0 + BL + kr * BROWB2 + nc * 8))       = make_uint2(l0, l1);
            split4(pb1, h0, h1, l0, l1);
            *(uint2*)(sm + (s0 + BH + (kr + 8) * BROWB2 + nc * 8)) = make_uint2(h0, h1);
            *(uint2*)(sm + (s0 + BL + (kr + 8) * BROWB2 + nc * 8)) = make_uint2(l0, l1);
        }
    };
    auto ldg_tiles = [&](int kt, float4& pa0, float4& pa1, float4& pb0, float4& pb1) {
        pa0 = *(const float4*)(Abase + (size_t)ar * KT + kt * 16 + ac * 4);
        pa1 = *(const float4*)(Abase + (size_t)(ar + 64) * KT + kt * 16 + ac * 4);
        if (FIRST) {
            pb0 = *(const float4*)(Bbase + (size_t)ar * DIM + kt * 16 + ac * 4);
            pb1 = *(const float4*)(Bbase + (size_t)(ar + 64) * DIM + kt * 16 + ac * 4);
        } else {
            pb0 = *(const float4*)(Bbase + (size_t)(kt * 16 + kr) * DIM + nc * 4);
            pb1 = *(const float4*)(Bbase + (size_t)(kt * 16 + kr + 8) * DIM + nc * 4);
        }
    };

    float acc[4][4][4];
#pragma unroll
    for (int m = 0; m < 4; m++)
#pragma unroll
        for (int n = 0; n < 4; n++)
#pragma unroll
            for (int j = 0; j < 4; j++) acc[m][n][j] = 0.f;

    // prologue: stage 0
    {
        float4 a0, a1, b0, b1;
        ldg_tiles(0, a0, a1, b0, b1);
        sts_stage(0, a0, a1, b0, b1);
    }
    __syncthreads();

    const int lrow = lane & 15;
    const int lkb  = lane & 16;         // second 16B chunk (k+8 / n+8)
    constexpr int I1 = FIRST ? 2 : 1;   // ntile0 second b-reg
    constexpr int J0 = FIRST ? 1 : 2;   // ntile1 first b-reg

    for (int kt = 0; kt < NT; kt++) {
        const uint32_t s0 = (kt & 1) * STAGE;

        float4 pa0, pa1, pb0, pb1;
        if (kt + 1 < NT) ldg_tiles(kt + 1, pa0, pa1, pb0, pb1);

        uint32_t ah[4][4], al[4][4];
#pragma unroll
        for (int mt = 0; mt < 4; mt++) {
            uint32_t ra = sb + s0 + AH + (wm * 64 + mt * 16 + lrow) * AROWB + lkb;
            ldm4(ra, ah[mt][0], ah[mt][1], ah[mt][2], ah[mt][3]);
            uint32_t rl = sb + s0 + AL + (wm * 64 + mt * 16 + lrow) * AROWB + lkb;
            ldm4(rl, al[mt][0], al[mt][1], al[mt][2], al[mt][3]);
        }
#pragma unroll
        for (int p = 0; p < 2; p++) {
            uint32_t bh[4], bl[4];
            if (FIRST) {
                uint32_t rb = sb + s0 + BH + (wn * 32 + p * 16 + lrow) * AROWB + lkb;
                ldm4(rb, bh[0], bh[1], bh[2], bh[3]);
                uint32_t rc = sb + s0 + BL + (wn * 32 + p * 16 + lrow) * AROWB + lkb;
                ldm4(rc, bl[0], bl[1], bl[2], bl[3]);
            } else {
                uint32_t rb = sb + s0 + BH + lrow * BROWB2 + (wn * 32 + p * 16) * 2 + lkb;
                ldm4t(rb, bh[0], bh[1], bh[2], bh[3]);
                uint32_t rc = sb + s0 + BL + lrow * BROWB2 + (wn * 32 + p * 16) * 2 + lkb;
                ldm4t(rc, bl[0], bl[1], bl[2], bl[3]);
            }
#pragma unroll
            for (int mt = 0; mt < 4; mt++) {
                mma16816(acc[mt][2 * p],     ah[mt][0], ah[mt][1], ah[mt][2], ah[mt][3], bh[0],  bh[I1]);
                mma16816(acc[mt][2 * p + 1], ah[mt][0], ah[mt][1], ah[mt][2], ah[mt][3], bh[J0], bh[3]);
                mma16816(acc[mt][2 * p],     al[mt][0], al[mt][1], al[mt][2], al[mt][3], bh[0],  bh[I1]);
                mma16816(acc[mt][2 * p + 1], al[mt][0], al[mt][1], al[mt][2], al[mt][3], bh[J0], bh[3]);
                mma16816(acc[mt][2 * p],     ah[mt][0], ah[mt][1], ah[mt][2], ah[mt][3], bl[0],  bl[I1]);
                mma16816(acc[mt][2 * p + 1], ah[mt][0], ah[mt][1], ah[mt][2], ah[mt][3], bl[J0], bl[3]);
            }
        }

        if (kt + 1 < NT) sts_stage(((kt + 1) & 1) * STAGE, pa0, pa1, pb0, pb1);
        __syncthreads();
    }

    // epilogue (standard m16n8 C layout)
    const size_t rbase = (size_t)b * LC + (size_t)yT * 128 + wm * 64 + (lane >> 2);
    const int    cbase = OUTOFF + xT * 128 + wn * 32 + (lane & 3) * 2;
#pragma unroll
    for (int mt = 0; mt < 4; mt++) {
#pragma unroll
        for (int nt = 0; nt < 4; nt++) {
            size_t r0 = (rbase + mt * 16) * OUTSTRIDE + cbase + nt * 8;
            *(float2*)(Cg + r0)                    = make_float2(acc[mt][nt][0], acc[mt][nt][1]);
            *(float2*)(Cg + r0 + 8ull * OUTSTRIDE) = make_float2(acc[mt][nt][2], acc[mt][nt][3]);
        }
    }

    // fused ctx copy into out LEFT half (GEMM2 only): this CTA's 128x128 tile
    if (!FIRST) {
        const float4* csrc = (const float4*)(actx + ((size_t)b * LC + (size_t)yT * 128) * DIM
                                             + (size_t)xT * 128);
        float4* cdst = (float4*)(gout + ((size_t)b * LC + (size_t)yT * 128) * (2 * DIM)
                                 + (size_t)xT * 128);
        const int crow = tid >> 5;      // 0..7
        const int ccol = tid & 31;      // 32 float4 = 128 floats
#pragma unroll
        for (int it = 0; it < 16; it++) {
            cdst[(size_t)(crow + it * 8) * (2 * DIM / 4) + ccol] =
                csrc[(size_t)(crow + it * 8) * (DIM / 4) + ccol];
        }
    }
}

// ---------------------------------------------------------------------------
// Warp-per-row softmax over 512 logits, in place in g_attn. 8 rows per block.
// ---------------------------------------------------------------------------
__global__ __launch_bounds__(256)
void ba_softmax(void)
{
    const int wid = threadIdx.x >> 5, lane = threadIdx.x & 31;
    const size_t row = (size_t)blockIdx.x * 8 + wid;
    float4* p = (float4*)(g_attn + row * LQ);

    float4 v[4];
    float mx = -1e30f;
#pragma unroll
    for (int i = 0; i < 4; i++) {
        v[i] = p[i * 32 + lane];
        mx = fmaxf(mx, fmaxf(fmaxf(v[i].x, v[i].y), fmaxf(v[i].z, v[i].w)));
    }
#pragma unroll
    for (int o = 16; o > 0; o >>= 1) mx = fmaxf(mx, __shfl_xor_sync(0xFFFFFFFFu, mx, o));

    float sum = 0.f;
#pragma unroll
    for (int i = 0; i < 4; i++) {
        v[i].x = __expf(v[i].x - mx); v[i].y = __expf(v[i].y - mx);
        v[i].z = __expf(v[i].z - mx); v[i].w = __expf(v[i].w - mx);
        sum += (v[i].x + v[i].y) + (v[i].z + v[i].w);
    }
#pragma unroll
    for (int o = 16; o > 0; o >>= 1) sum += __shfl_xor_sync(0xFFFFFFFFu, sum, o);

    const float inv = 1.0f / sum;
#pragma unroll
    for (int i = 0; i < 4; i++) {
        v[i].x *= inv; v[i].y *= inv; v[i].z *= inv; v[i].w *= inv;
        p[i * 32 + lane] = v[i];
    }
}

// ---------------------------------------------------------------------------
extern "C" void kernel_launch(void* const* d_in, const int* in_sizes, int n_in,
                              void* d_out, int out_size)
{
    const float* question = (const float*)d_in[0];
    const float* context  = (const float*)d_in[1];
    if (in_sizes[0] > in_sizes[1]) {
        const float* t = question; question = context; context = t;
    }
    float* out = (float*)d_out;

    // logits = ctx @ q^T -> g_attn (bound in device code)
    ba_mma<true><<<dim3(LQ / 128, LC / 128, BATCH), 256>>>(context, question, nullptr);
    // softmax in place (fp32), warp per row
    ba_softmax<<<BATCH * LC / 8, 256>>>();
    // attn_out = w @ q -> right half of out, + fused ctx copy -> left half
    ba_mma<false><<<dim3(DIM / 128, LC / 128, BATCH), 256>>>(context, question, out);
}